// round 15
// baseline (speedup 1.0000x reference)
#include <cuda_runtime.h>
#include <cuda_bf16.h>

#define B_    2
#define T_    8192
#define D_    1024
#define H_    4
#define HD_   256
#define C_    64
#define N_    128
#define BH_   8

typedef unsigned long long ull;

__device__ __forceinline__ ull pk2(float a, float b) {
    ull r; asm("mov.b64 %0, {%1, %2};" : "=l"(r) : "f"(a), "f"(b)); return r;
}
__device__ __forceinline__ float2 upk2(ull v) {
    float2 f; asm("mov.b64 {%0, %1}, %2;" : "=f"(f.x), "=f"(f.y) : "l"(v)); return f;
}
__device__ __forceinline__ ull fma2(ull a, ull b, ull c) {
    ull d; asm("fma.rn.f32x2 %0, %1, %2, %3;" : "=l"(d) : "l"(a), "l"(b), "l"(c)); return d;
}
__device__ __forceinline__ ull add2(ull a, ull b) {
    ull d; asm("add.rn.f32x2 %0, %1, %2;" : "=l"(d) : "l"(a), "l"(b)); return d;
}
#define SGN2 0x8000000080000000ULL

__device__ __forceinline__ unsigned smem_u32(const void* p) {
    unsigned a;
    asm("{ .reg .u64 t; cvta.to.shared.u64 t, %1; cvt.u32.u64 %0, t; }" : "=r"(a) : "l"(p));
    return a;
}
#define LDSM4(r, addr) \
    asm volatile("ldmatrix.sync.aligned.m8n8.x4.shared.b16 {%0,%1,%2,%3}, [%4];" \
        : "=r"((r)[0]), "=r"((r)[1]), "=r"((r)[2]), "=r"((r)[3]) : "r"(addr))
#define MMA16816(d, a, b0v, b1v) \
    asm volatile("mma.sync.aligned.m16n8k16.row.col.f32.bf16.bf16.f32 " \
        "{%0,%1,%2,%3}, {%4,%5,%6,%7}, {%8,%9}, {%0,%1,%2,%3};" \
        : "+f"((d)[0]), "+f"((d)[1]), "+f"((d)[2]), "+f"((d)[3]) \
        : "r"((a)[0]), "r"((a)[1]), "r"((a)[2]), "r"((a)[3]), "r"(b0v), "r"(b1v))
#define CPA16(dst, src) \
    asm volatile("cp.async.cg.shared.global [%0], [%1], 16;" :: "r"(dst), "l"(src))
#define CPCOMMIT() asm volatile("cp.async.commit_group;")
#define CPWAIT2()  asm volatile("cp.async.wait_group 2;")
#define CPWAIT1()  asm volatile("cp.async.wait_group 1;")
#define CPWAIT0()  asm volatile("cp.async.wait_group 0;")

// ---------------- device scratch ----------------
__device__ float g_v[(size_t)B_ * T_ * D_];
__device__ float g_rk[(size_t)BH_ * T_ * HD_];
__device__ float g_vcorr[(size_t)BH_ * N_ * C_ * HD_];
__device__ float g_gpow[H_][C_ + 1];
__device__ float g_alpha[H_];
__device__ __nv_bfloat16 g_xb [(size_t)B_ * T_ * D_];
__device__ __nv_bfloat16 g_ob [(size_t)B_ * T_ * D_];
__device__ __nv_bfloat16 g_Wwb[(size_t)D_ * D_];
__device__ __nv_bfloat16 g_Wrb[(size_t)D_ * D_];
__device__ __nv_bfloat16 g_rkb   [(size_t)BH_ * T_ * HD_];
__device__ __nv_bfloat16 g_wkcA_b[(size_t)BH_ * N_ * C_ * HD_];
__device__ __nv_bfloat16 g_intra_b[(size_t)BH_ * N_ * C_ * C_];
__device__ __nv_bfloat16 g_wkgT  [(size_t)BH_ * N_ * HD_ * C_];

__global__ __launch_bounds__(256) void conv_bf16(const float* __restrict__ in,
                                                 __nv_bfloat16* __restrict__ out) {
    size_t i = ((size_t)blockIdx.x * 256 + threadIdx.x) * 8;
    float4 a = *(const float4*)(in + i);
    float4 b = *(const float4*)(in + i + 4);
    __nv_bfloat162 r0 = __floats2bfloat162_rn(a.x, a.y);
    __nv_bfloat162 r1 = __floats2bfloat162_rn(a.z, a.w);
    __nv_bfloat162 r2 = __floats2bfloat162_rn(b.x, b.y);
    __nv_bfloat162 r3 = __floats2bfloat162_rn(b.z, b.w);
    uint4 pk;
    pk.x = *(unsigned*)&r0; pk.y = *(unsigned*)&r1;
    pk.z = *(unsigned*)&r2; pk.w = *(unsigned*)&r3;
    *(uint4*)(out + i) = pk;
}

// rk normalize + x->bf16, FUSED with Ww->bf16 conversion and setup.
// blocks [0, 8192): rk work; blocks [8192, 8704): convert Ww (2048 elems each).
__global__ __launch_bounds__(256) void rk_fused_kernel(const float* __restrict__ x,
                                                       const float* __restrict__ Ww,
                                                       const float* __restrict__ decay,
                                                       const float* __restrict__ log_alpha) {
    if (blockIdx.x >= 8192) {
        int cb = blockIdx.x - 8192;
        if (cb == 0 && threadIdx.x < H_) {
            int h = threadIdx.x;
            float g = 1.f / (1.f + expf(-decay[h]));
            g_alpha[h] = expf(log_alpha[h]);
            float p = 1.f;
            for (int i = 0; i <= C_; i++) { g_gpow[h][i] = p; p *= g; }
        }
        size_t i = ((size_t)cb * 256 + threadIdx.x) * 8;
        float4 a = *(const float4*)(Ww + i);
        float4 b = *(const float4*)(Ww + i + 4);
        __nv_bfloat162 r0 = __floats2bfloat162_rn(a.x, a.y);
        __nv_bfloat162 r1 = __floats2bfloat162_rn(a.z, a.w);
        __nv_bfloat162 r2 = __floats2bfloat162_rn(b.x, b.y);
        __nv_bfloat162 r3 = __floats2bfloat162_rn(b.z, b.w);
        uint4 pk;
        pk.x = *(unsigned*)&r0; pk.y = *(unsigned*)&r1;
        pk.z = *(unsigned*)&r2; pk.w = *(unsigned*)&r3;
        *(uint4*)(g_Wwb + i) = pk;
        return;
    }
    int warp = threadIdx.x >> 5, lane = threadIdx.x & 31;
    int row = blockIdx.x * 8 + warp;
    int h  = row & (H_ - 1);
    int bt = row >> 2;
    const float* xp = x + (size_t)bt * D_ + h * HD_ + lane * 8;
    float4 v0 = *(const float4*)(xp);
    float4 v1 = *(const float4*)(xp + 4);
    {
        __nv_bfloat162 q0 = __floats2bfloat162_rn(v0.x, v0.y);
        __nv_bfloat162 q1 = __floats2bfloat162_rn(v0.z, v0.w);
        __nv_bfloat162 q2 = __floats2bfloat162_rn(v1.x, v1.y);
        __nv_bfloat162 q3 = __floats2bfloat162_rn(v1.z, v1.w);
        uint4 pk;
        pk.x = *(unsigned*)&q0; pk.y = *(unsigned*)&q1;
        pk.z = *(unsigned*)&q2; pk.w = *(unsigned*)&q3;
        *(uint4*)(g_xb + (size_t)bt * D_ + h * HD_ + lane * 8) = pk;
    }
    float ss = v0.x*v0.x + v0.y*v0.y + v0.z*v0.z + v0.w*v0.w
             + v1.x*v1.x + v1.y*v1.y + v1.z*v1.z + v1.w*v1.w;
    #pragma unroll
    for (int o = 16; o; o >>= 1) ss += __shfl_xor_sync(0xffffffffu, ss, o);
    float inv = 1.f / fmaxf(sqrtf(ss), 1e-12f);
    int b = bt >> 13, t = bt & (T_ - 1);
    size_t base = ((size_t)(b * H_ + h) * T_ + t) * HD_ + lane * 8;
    float4 o0 = make_float4(v0.x*inv, v0.y*inv, v0.z*inv, v0.w*inv);
    float4 o1 = make_float4(v1.x*inv, v1.y*inv, v1.z*inv, v1.w*inv);
    *(float4*)(g_rk + base)     = o0;
    *(float4*)(g_rk + base + 4) = o1;
    __nv_bfloat162 q0 = __floats2bfloat162_rn(o0.x, o0.y);
    __nv_bfloat162 q1 = __floats2bfloat162_rn(o0.z, o0.w);
    __nv_bfloat162 q2 = __floats2bfloat162_rn(o1.x, o1.y);
    __nv_bfloat162 q3 = __floats2bfloat162_rn(o1.z, o1.w);
    uint4 pk;
    pk.x = *(unsigned*)&q0; pk.y = *(unsigned*)&q1;
    pk.z = *(unsigned*)&q2; pk.w = *(unsigned*)&q3;
    *(uint4*)(g_rkb + base) = pk;
}

// ---------------- bf16 GEMM (TN), cp.async 2-stage (proven R9) -------------
#define RSE 40
#define STG_B (128 * RSE * 2)
__global__ __launch_bounds__(256, 2) void gemm_bf16_tn(const __nv_bfloat16* __restrict__ A,
                                                       const __nv_bfloat16* __restrict__ W,
                                                       const float* __restrict__ Cin,
                                                       float* __restrict__ Cout) {
    __shared__ __nv_bfloat16 As[2][128 * RSE];
    __shared__ __nv_bfloat16 Bs[2][128 * RSE];
    const int tid = threadIdx.x;
    const int bm = blockIdx.y * 128, bn = blockIdx.x * 128;
    const int wid = tid >> 5, lane = tid & 31;
    const int wm = (wid & 3) * 32, wn = (wid >> 2) * 64;
    const int lr = tid >> 2, lk = (tid & 3) * 8;
    const __nv_bfloat16* Ap0 = A + (size_t)(bm + lr) * D_ + lk;
    const __nv_bfloat16* Ap1 = A + (size_t)(bm + lr + 64) * D_ + lk;
    const __nv_bfloat16* Wp0 = W + (size_t)(bn + lr) * D_ + lk;
    const __nv_bfloat16* Wp1 = W + (size_t)(bn + lr + 64) * D_ + lk;
    const unsigned dA = smem_u32(&As[0][lr * RSE + lk]);
    const unsigned dB = smem_u32(&Bs[0][lr * RSE + lk]);
    const unsigned a_base = smem_u32(As) +
        (unsigned)((wm + (lane & 7) + ((lane >> 3) & 1) * 8) * (RSE * 2) + (lane >> 4) * 16);
    const unsigned b_base = smem_u32(Bs) +
        (unsigned)((wn + (lane & 7) + ((lane >> 4) & 1) * 8) * (RSE * 2) + ((lane >> 3) & 1) * 16);

    float acc[2][8][4];
    #pragma unroll
    for (int mt = 0; mt < 2; mt++)
        #pragma unroll
        for (int nt = 0; nt < 8; nt++)
            #pragma unroll
            for (int q = 0; q < 4; q++) acc[mt][nt][q] = 0.f;

    auto loadStage = [&](int s, int k0) {
        CPA16(dA + s * STG_B, Ap0 + k0);
        CPA16(dA + s * STG_B + 64 * RSE * 2, Ap1 + k0);
        CPA16(dB + s * STG_B, Wp0 + k0);
        CPA16(dB + s * STG_B + 64 * RSE * 2, Wp1 + k0);
    };

    loadStage(0, 0);  CPCOMMIT();
    loadStage(1, 32); CPCOMMIT();

    for (int i = 0; i < 32; i++) {
        if (i < 31) { CPWAIT1(); } else { CPWAIT0(); }
        __syncthreads();
        const unsigned sa = a_base + (i & 1) * STG_B;
        const unsigned sbb = b_base + (i & 1) * STG_B;
        #pragma unroll
        for (int kk = 0; kk < 2; kk++) {
            unsigned ka = sa + kk * 32, kb = sbb + kk * 32;
            unsigned af[2][4], bf[4][4];
            #pragma unroll
            for (int mt = 0; mt < 2; mt++) LDSM4(af[mt], ka + mt * 16 * (RSE * 2));
            #pragma unroll
            for (int j = 0; j < 4; j++) LDSM4(bf[j], kb + j * 16 * (RSE * 2));
            #pragma unroll
            for (int mt = 0; mt < 2; mt++)
                #pragma unroll
                for (int nt = 0; nt < 8; nt++)
                    MMA16816(acc[mt][nt], af[mt],
                             bf[nt >> 1][(nt & 1) * 2 + 0], bf[nt >> 1][(nt & 1) * 2 + 1]);
        }
        __syncthreads();
        if (i + 2 < 32) { loadStage(i & 1, (i + 2) * 32); CPCOMMIT(); }
    }

    const int rr = lane >> 2, cc = (lane & 3) * 2;
    #pragma unroll
    for (int mt = 0; mt < 2; mt++) {
        int row = bm + wm + mt * 16 + rr;
        #pragma unroll
        for (int nt = 0; nt < 8; nt++) {
            int col = bn + wn + nt * 8 + cc;
            float2 lo = make_float2(acc[mt][nt][0], acc[mt][nt][1]);
            float2 hi = make_float2(acc[mt][nt][2], acc[mt][nt][3]);
            if (Cin) {
                float2 c0 = *(const float2*)(Cin + (size_t)row * D_ + col);
                float2 c1 = *(const float2*)(Cin + (size_t)(row + 8) * D_ + col);
                lo.x += c0.x; lo.y += c0.y; hi.x += c1.x; hi.y += c1.y;
            }
            *(float2*)(Cout + (size_t)row * D_ + col)       = lo;
            *(float2*)(Cout + (size_t)(row + 8) * D_ + col) = hi;
        }
    }
}

// ---------------- chunk prep: MMA phase 1 + forward substitution ------------
#define PSTK 0
#define PWL  34320
#define PGP  51728
#define PREP_SMEM 52096
__global__ __launch_bounds__(256) void prep_kernel() {
    extern __shared__ char smc[];
    const unsigned sb = smem_u32(smc);
    float* Wl  = (float*)(smc + PWL);
    float* gps = (float*)(smc + PGP);
    const int tid = threadIdx.x, wid = tid >> 5, lane = tid & 31;
    const int n  = blockIdx.x & (N_ - 1);
    const int bh = blockIdx.x >> 7;
    const int b  = bh >> 2, h = bh & 3;
    if (tid <= C_) gps[tid] = g_gpow[h][tid];

    const __nv_bfloat16* gRkb = g_rkb + (size_t)bh * T_ * HD_;
    const int t0 = n * C_ - 1;
    {
        int r = tid >> 2, seg = (tid & 3) * 64;
        int grow = t0 + r; if (grow < 0) grow = 0;
        unsigned d = sb + PSTK + r * 528 + seg * 2;
        const __nv_bfloat16* s = gRkb + (size_t)grow * HD_ + seg;
        #pragma unroll
        for (int q = 0; q < 8; q++) CPA16(d + q * 16, s + q * 8);
        if (tid < 4) {
            unsigned d2 = sb + PSTK + 64 * 528 + tid * 128;
            const __nv_bfloat16* s2 = gRkb + (size_t)(t0 + 64) * HD_ + tid * 64;
            #pragma unroll
            for (int q = 0; q < 8; q++) CPA16(d2 + q * 16, s2 + q * 8);
        }
    }
    CPCOMMIT(); CPWAIT0();
    __syncthreads();
    if (t0 < 0 && tid < 32) *(uint4*)(smc + PSTK + tid * 16) = make_uint4(0,0,0,0);
    __syncthreads();

    float acc[8][4];
    #pragma unroll
    for (int nt = 0; nt < 8; nt++)
        #pragma unroll
        for (int q = 0; q < 4; q++) acc[nt][q] = 0.f;
    {
        const unsigned abase = sb + PSTK +
            ((wid & 3) * 16 + (lane & 15) + (wid >= 4 ? 1 : 0)) * 528 + (lane >> 4) * 16;
        const unsigned bbase = sb + PSTK +
            ((lane & 7) + ((lane >> 4) & 1) * 8) * 528 + ((lane >> 3) & 1) * 16;
        #pragma unroll
        for (int k = 0; k < 16; k++) {
            unsigned af[4], bf4[4][4];
            LDSM4(af, abase + k * 32);
            #pragma unroll
            for (int j = 0; j < 4; j++) LDSM4(bf4[j], bbase + j * 16 * 528 + k * 32);
            #pragma unroll
            for (int nt = 0; nt < 8; nt++)
                MMA16816(acc[nt], af,
                         bf4[nt >> 1][(nt & 1) * 2 + 0], bf4[nt >> 1][(nt & 1) * 2 + 1]);
        }
    }
    size_t ib = ((size_t)(bh * N_ + n)) * C_;
    {
        const int rr = lane >> 2, cq = (lane & 3) * 2;
        const int i0 = (wid & 3) * 16 + rr;
        #pragma unroll
        for (int nt = 0; nt < 8; nt++) {
            int j = nt * 8 + cq;
            #pragma unroll
            for (int half = 0; half < 2; half++) {
                int i = i0 + half * 8;
                float v0 = acc[nt][half * 2 + 0], v1 = acc[nt][half * 2 + 1];
                float l0 = (j < i)     ? gps[i - j]     : 0.f;
                float l1 = (j + 1 < i) ? gps[i - j - 1] : 0.f;
                if (wid < 4) {
                    Wl[i * 68 + j]     = v0 * l0;
                    Wl[i * 68 + j + 1] = v1 * l1;
                } else {
                    *(__nv_bfloat162*)&g_intra_b[(ib + i) * C_ + j] =
                        __floats2bfloat162_rn(v0 * l0, v1 * l1);
                }
            }
        }
    }
    __syncthreads();

    const int c = tid;
    ull bvw[C_];
    const size_t wgbase = ((size_t)(bh * N_ + n) * HD_ + c) * C_;
    #pragma unroll
    for (int i2 = 0; i2 < C_ / 2; i2++) {
        int i = 2 * i2;
        float bv0 = g_v[((size_t)b * T_ + n * C_ + i) * D_ + h * HD_ + c];
        float bv1 = g_v[((size_t)b * T_ + n * C_ + i + 1) * D_ + h * HD_ + c];
        int tw0 = n * C_ + i - 1;
        float bw0 = (tw0 >= 0) ? g_rk[((size_t)bh * T_ + tw0) * HD_ + c] : 0.f;
        float bw1 = g_rk[((size_t)bh * T_ + tw0 + 1) * HD_ + c];
        bvw[i]     = pk2(bv0, bw0);
        bvw[i + 1] = pk2(bv1, bw1);
        __nv_bfloat162 wp;
        wp.x = __float2bfloat16(bw0 * gps[63 - i]);
        wp.y = __float2bfloat16(bw1 * gps[62 - i]);
        *(__nv_bfloat162*)&g_wkgT[wgbase + i] = wp;
    }
    #pragma unroll
    for (int i = 1; i < C_; i++) {
        ull a = 0ULL;
        #pragma unroll
        for (int j4 = 0; j4 < i; j4 += 4) {
            float4 w = *(const float4*)&Wl[i * 68 + j4];
            a = fma2(pk2(w.x, w.x), bvw[j4],     a);
            a = fma2(pk2(w.y, w.y), bvw[j4 + 1], a);
            a = fma2(pk2(w.z, w.z), bvw[j4 + 2], a);
            a = fma2(pk2(w.w, w.w), bvw[j4 + 3], a);
        }
        bvw[i] = add2(bvw[i], a ^ SGN2);
    }
    #pragma unroll
    for (int i = 0; i < C_; i++) {
        float2 f = upk2(bvw[i]);
        g_vcorr [(ib + i) * HD_ + c] = f.x;
        g_wkcA_b[(ib + i) * HD_ + c] = __float2bfloat16(f.y);
    }
}

// ---------------- MMA chunk scan: 128 CTAs x 512 threads (R13 champion) ----
#define AST_OFF  0
#define AST_BUF  67584
#define WGT_OFF  135168
#define SB_OFF   172032
#define VNT_OFF  180480
#define INT_OFF  182784
#define VCO_OFF  192000
#define PART_OFF 201216
#define GP_OFF   209408
#define SCAN_SMEM 209920

__global__ void __launch_bounds__(512, 1) scan_mma_kernel() {
    extern __shared__ char smc[];
    const unsigned sb = smem_u32(smc);
    const int tid = threadIdx.x, wid = tid >> 5, lane = tid & 31;
    const int bh = blockIdx.y, c0 = blockIdx.x * 16;
    const int b = bh >> 2, h = bh & 3;
    float* gps = (float*)(smc + GP_OFF);
    if (tid <= C_) gps[tid] = g_gpow[h][tid];
    if (tid == C_ + 1) gps[C_ + 1] = g_alpha[h];

    const __nv_bfloat16* gWkc = g_wkcA_b + (size_t)bh * N_ * C_ * HD_;
    const __nv_bfloat16* gRk  = g_rkb    + (size_t)bh * T_ * HD_;
    const __nv_bfloat16* gWg  = g_wkgT   + (size_t)bh * N_ * HD_ * C_;
    const __nv_bfloat16* gIn  = g_intra_b+ (size_t)bh * N_ * C_ * C_;
    const float*         gVc  = g_vcorr  + (size_t)bh * N_ * C_ * HD_;

    auto copyG1 = [&](int n) {
        int r = tid >> 2, q = tid & 3;
        unsigned d = sb + AST_OFF + (n & 1) * AST_BUF + r * 528 + q * 128;
        const __nv_bfloat16* s = (r < 64)
            ? gWkc + ((size_t)n * C_ + r) * HD_ + q * 64
            : gRk  + ((size_t)n * C_ + (r - 64)) * HD_ + q * 64;
        #pragma unroll
        for (int i = 0; i < 8; i++) CPA16(d + i * 16, s + i * 8);
    };
    auto copyG2 = [&](int n) {
        {
            int r = tid >> 1, half = tid & 1;
            unsigned d = sb + WGT_OFF + r * 144 + half * 64;
            const __nv_bfloat16* s = gWg + ((size_t)n * HD_ + r) * C_ + half * 32;
            #pragma unroll
            for (int i = 0; i < 4; i++) CPA16(d + i * 16, s + i * 8);
        }
        {
            int row = tid >> 3, seg = tid & 7;
            CPA16(sb + INT_OFF + row * 144 + seg * 16,
                  gIn + ((size_t)n * C_ + row) * C_ + seg * 8);
        }
        if (tid < 256) {
            int row = tid >> 2, seg = tid & 3;
            CPA16(sb + VCO_OFF + row * 144 + seg * 16,
                  gVc + ((size_t)n * C_ + row) * HD_ + c0 + seg * 4);
        }
    };

    const int rt = wid & 7, kh = wid >> 3;
    const unsigned aA = sb + AST_OFF + (rt * 16 + (lane & 15)) * 528 + (lane >> 4) * 16 + kh * 256;
    const unsigned bS = sb + SB_OFF + ((lane & 7) + ((lane >> 4) & 1) * 8) * 528 + ((lane >> 3) & 1) * 16 + kh * 256;
    const unsigned aV = sb + VNT_OFF + (lane & 15) * 144 + (lane >> 4) * 16;
    const unsigned bW = sb + WGT_OFF + (wid * 16 + (lane & 7) + ((lane >> 4) & 1) * 8) * 144 + ((lane >> 3) & 1) * 16;
    const unsigned aI = sb + INT_OFF + ((wid & 3) * 16 + (lane & 15)) * 144 + (lane >> 4) * 16;
    const unsigned bV = sb + VNT_OFF + ((lane & 7) + ((lane >> 4) & 1) * 8) * 144 + ((lane >> 3) & 1) * 16;
    float* part = (float*)(smc + PART_OFF);

    float Sacc[2][4] = {};
    copyG1(0); CPCOMMIT();
    copyG2(0); CPCOMMIT();

    for (int n = 0; n < N_; n++) {
        #pragma unroll
        for (int nt = 0; nt < 2; nt++) {
            int c = lane >> 2;
            int ks = wid * 16 + nt * 8 + (lane & 3) * 2;
            *(__nv_bfloat162*)(smc + SB_OFF + c * 528 + ks * 2) =
                __floats2bfloat162_rn(Sacc[nt][0], Sacc[nt][1]);
            *(__nv_bfloat162*)(smc + SB_OFF + (c + 8) * 528 + ks * 2) =
                __floats2bfloat162_rn(Sacc[nt][2], Sacc[nt][3]);
        }
        if (n + 1 < N_) copyG1(n + 1);
        CPCOMMIT();
        CPWAIT2();
        __syncthreads();

        float accA[2][4] = {};
        {
            unsigned ab = aA + (n & 1) * AST_BUF;
            #pragma unroll
            for (int k = 0; k < 8; k++) {
                unsigned af[4], b0[4];
                LDSM4(af, ab + k * 32);
                LDSM4(b0, bS + k * 32);
                MMA16816(accA[0], af, b0[0], b0[1]);
                MMA16816(accA[1], af, b0[2], b0[3]);
            }
        }
        if (wid >= 8) {
            float* pp = part + (wid - 8) * 256 + lane * 8;
            *(float4*)pp       = make_float4(accA[0][0], accA[0][1], accA[0][2], accA[0][3]);
            *(float4*)(pp + 4) = make_float4(accA[1][0], accA[1][1], accA[1][2], accA[1][3]);
        }
        CPWAIT1();
        __syncthreads();

        int r0 = (wid & 3) * 16 + (lane >> 2);
        if (wid < 8) {
            float* pp = part + wid * 256 + lane * 8;
            float4 p0 = *(float4*)pp, p1 = *(float4*)(pp + 4);
            accA[0][0] += p0.x; accA[0][1] += p0.y; accA[0][2] += p0.z; accA[0][3] += p0.w;
            accA[1][0] += p1.x; accA[1][1] += p1.y; accA[1][2] += p1.z; accA[1][3] += p1.w;
        }
        if (wid < 4) {
            #pragma unroll
            for (int nt = 0; nt < 2; nt++) {
                int cc = nt * 8 + (lane & 3) * 2;
                float2 v0 = *(float2*)(smc + VCO_OFF + r0 * 144 + cc * 4);
                float2 v1 = *(float2*)(smc + VCO_OFF + (r0 + 8) * 144 + cc * 4);
                *(__nv_bfloat16*)(smc + VNT_OFF + cc * 144 + r0 * 2)       = __float2bfloat16(v0.x - accA[nt][0]);
                *(__nv_bfloat16*)(smc + VNT_OFF + (cc + 1) * 144 + r0 * 2) = __float2bfloat16(v0.y - accA[nt][1]);
                *(__nv_bfloat16*)(smc + VNT_OFF + cc * 144 + (r0 + 8) * 2)       = __float2bfloat16(v1.x - accA[nt][2]);
                *(__nv_bfloat16*)(smc + VNT_OFF + (cc + 1) * 144 + (r0 + 8) * 2) = __float2bfloat16(v1.y - accA[nt][3]);
            }
        } else if (wid < 8) {
            float g0 = gps[r0], g1 = gps[r0 + 8];
            #pragma unroll
            for (int nt = 0; nt < 2; nt++) {
                accA[nt][0] *= g0; accA[nt][1] *= g0;
                accA[nt][2] *= g1; accA[nt][3] *= g1;
            }
        }
        __syncthreads();

        if (wid >= 4 && wid < 8) {
            #pragma unroll
            for (int k = 0; k < 4; k++) {
                unsigned ai[4], v0[4];
                LDSM4(ai, aI + k * 32);
                LDSM4(v0, bV + k * 32);
                MMA16816(accA[0], ai, v0[0], v0[1]);
                MMA16816(accA[1], ai, v0[2], v0[3]);
            }
            float al = gps[C_ + 1];
            size_t ob = ((size_t)b * T_ + n * C_) * D_ + h * HD_ + c0;
            #pragma unroll
            for (int nt = 0; nt < 2; nt++) {
                int cc = nt * 8 + (lane & 3) * 2;
                *(__nv_bfloat162*)(g_ob + ob + (size_t)r0 * D_ + cc) =
                    __floats2bfloat162_rn(accA[nt][0] * al, accA[nt][1] * al);
                *(__nv_bfloat162*)(g_ob + ob + (size_t)(r0 + 8) * D_ + cc) =
                    __floats2bfloat162_rn(accA[nt][2] * al, accA[nt][3] * al);
            }
        }

        {
            float gC = gps[C_];
            #pragma unroll
            for (int nt = 0; nt < 2; nt++)
                #pragma unroll
                for (int q = 0; q < 4; q++) Sacc[nt][q] *= gC;
            #pragma unroll
            for (int k = 0; k < 4; k++) {
                unsigned a0[4], w0[4];
                LDSM4(a0, aV + k * 32);
                LDSM4(w0, bW + k * 32);
                MMA16816(Sacc[0], a0, w0[0], w0[1]);
                MMA16816(Sacc[1], a0, w0[2], w0[3]);
            }
        }
        __syncthreads();
        if (n + 1 < N_) copyG2(n + 1);
        CPCOMMIT();
    }
}

// ---------------- launch ----------------
extern "C" void kernel_launch(void* const* d_in, const int* in_sizes, int n_in,
                              void* d_out, int out_size) {
    const float* x     = (const float*)d_in[0];
    const float* Ww    = (const float*)d_in[1];
    const float* Wr    = (const float*)d_in[2];
    const float* decay = (const float*)d_in[3];
    const float* lalp  = (const float*)d_in[4];
    float* out = (float*)d_out;

    cudaFuncSetAttribute(scan_mma_kernel, cudaFuncAttributeMaxDynamicSharedMemorySize,
                         SCAN_SMEM);
    cudaFuncSetAttribute(prep_kernel, cudaFuncAttributeMaxDynamicSharedMemorySize,
                         PREP_SMEM);

    void *pv = nullptr, *pxb = nullptr, *pob = nullptr, *pwwb = nullptr, *pwrb = nullptr;
    cudaGetSymbolAddress(&pv, g_v);
    cudaGetSymbolAddress(&pxb, g_xb);
    cudaGetSymbolAddress(&pob, g_ob);
    cudaGetSymbolAddress(&pwwb, g_Wwb);
    cudaGetSymbolAddress(&pwrb, g_Wrb);

    const size_t NW = (size_t)D_ * D_;

    // launch order puts scan at profiled index 3
    rk_fused_kernel<<<8192 + 512, 256>>>(x, Ww, decay, lalp);
    gemm_bf16_tn<<<dim3(D_ / 128, (B_ * T_) / 128), 256>>>(
        (const __nv_bfloat16*)pxb, (const __nv_bfloat16*)pwwb, nullptr, (float*)pv);
    prep_kernel<<<BH_ * N_, 256, PREP_SMEM>>>();
    scan_mma_kernel<<<dim3(16, BH_), 512, SCAN_SMEM>>>();
    conv_bf16<<<(int)(NW / 2048), 256>>>(Wr, (__nv_bfloat16*)pwrb);
    gemm_bf16_tn<<<dim3(D_ / 128, (B_ * T_) / 128), 256>>>(
        (const __nv_bfloat16*)pob, (const __nv_bfloat16*)pwrb, x, out);
}

// round 17
// speedup vs baseline: 1.0993x; 1.0993x over previous
#include <cuda_runtime.h>
#include <cuda_bf16.h>

#define B_    2
#define T_    8192
#define D_    1024
#define H_    4
#define HD_   256
#define C_    64
#define N_    128
#define BH_   8

typedef unsigned long long ull;

__device__ __forceinline__ ull pk2(float a, float b) {
    ull r; asm("mov.b64 %0, {%1, %2};" : "=l"(r) : "f"(a), "f"(b)); return r;
}
__device__ __forceinline__ float2 upk2(ull v) {
    float2 f; asm("mov.b64 {%0, %1}, %2;" : "=f"(f.x), "=f"(f.y) : "l"(v)); return f;
}
__device__ __forceinline__ ull fma2(ull a, ull b, ull c) {
    ull d; asm("fma.rn.f32x2 %0, %1, %2, %3;" : "=l"(d) : "l"(a), "l"(b), "l"(c)); return d;
}
__device__ __forceinline__ ull add2(ull a, ull b) {
    ull d; asm("add.rn.f32x2 %0, %1, %2;" : "=l"(d) : "l"(a), "l"(b)); return d;
}
#define SGN2 0x8000000080000000ULL

__device__ __forceinline__ unsigned smem_u32(const void* p) {
    unsigned a;
    asm("{ .reg .u64 t; cvta.to.shared.u64 t, %1; cvt.u32.u64 %0, t; }" : "=r"(a) : "l"(p));
    return a;
}
#define LDSM4(r, addr) \
    asm volatile("ldmatrix.sync.aligned.m8n8.x4.shared.b16 {%0,%1,%2,%3}, [%4];" \
        : "=r"((r)[0]), "=r"((r)[1]), "=r"((r)[2]), "=r"((r)[3]) : "r"(addr))
#define MMA16816(d, a, b0v, b1v) \
    asm volatile("mma.sync.aligned.m16n8k16.row.col.f32.bf16.bf16.f32 " \
        "{%0,%1,%2,%3}, {%4,%5,%6,%7}, {%8,%9}, {%0,%1,%2,%3};" \
        : "+f"((d)[0]), "+f"((d)[1]), "+f"((d)[2]), "+f"((d)[3]) \
        : "r"((a)[0]), "r"((a)[1]), "r"((a)[2]), "r"((a)[3]), "r"(b0v), "r"(b1v))
#define CPA16(dst, src) \
    asm volatile("cp.async.cg.shared.global [%0], [%1], 16;" :: "r"(dst), "l"(src))
#define CPCOMMIT() asm volatile("cp.async.commit_group;")
#define CPWAIT1()  asm volatile("cp.async.wait_group 1;")
#define CPWAIT0()  asm volatile("cp.async.wait_group 0;")

// ---- TMA bulk (1D) + mbarrier helpers ----
#define CPBULK(dst, src, bytes, mbar) \
    asm volatile("cp.async.bulk.shared::cluster.global.mbarrier::complete_tx::bytes " \
        "[%0], [%1], %2, [%3];" \
        :: "r"(dst), "l"(src), "r"(bytes), "r"(mbar) : "memory")
#define MBAR_INIT(addr, cnt) \
    asm volatile("mbarrier.init.shared.b64 [%0], %1;" :: "r"(addr), "r"(cnt) : "memory")
#define MBAR_EXPECT(addr, bytes) \
    asm volatile("mbarrier.arrive.expect_tx.shared.b64 _, [%0], %1;" \
        :: "r"(addr), "r"(bytes) : "memory")
#define MBAR_WAIT(mbar, ph) do { \
    unsigned _m = (mbar); unsigned _p = (ph); unsigned _done; \
    asm volatile("{\n\t.reg .pred p;\n\t" \
        "mbarrier.try_wait.parity.acquire.cta.shared::cta.b64 p, [%1], %2;\n\t" \
        "selp.b32 %0, 1, 0, p;\n\t}" : "=r"(_done) : "r"(_m), "r"(_p) : "memory"); \
    if (!_done) { \
        asm volatile("{\n\t.reg .pred P1;\n\t" \
            "WL%=:\n\t" \
            "mbarrier.try_wait.parity.acquire.cta.shared::cta.b64 P1, [%0], %1, 0x989680;\n\t" \
            "@P1 bra.uni WD%=;\n\t" \
            "bra.uni WL%=;\n\t" \
            "WD%=:\n\t}" :: "r"(_m), "r"(_p) : "memory"); \
    } \
} while (0)

// ---------------- device scratch ----------------
__device__ float g_v[(size_t)B_ * T_ * D_];
__device__ float g_rk[(size_t)BH_ * T_ * HD_];
__device__ float g_vcorr[(size_t)BH_ * N_ * C_ * HD_];
__device__ float g_gpow[H_][C_ + 1];
__device__ float g_alpha[H_];
__device__ __nv_bfloat16 g_xb [(size_t)B_ * T_ * D_];
__device__ __nv_bfloat16 g_ob [(size_t)B_ * T_ * D_];
__device__ __nv_bfloat16 g_Wwb[(size_t)D_ * D_];
__device__ __nv_bfloat16 g_Wrb[(size_t)D_ * D_];
__device__ __nv_bfloat16 g_rkb   [(size_t)BH_ * T_ * HD_];
__device__ __nv_bfloat16 g_wkcA_b[(size_t)BH_ * N_ * C_ * HD_];
__device__ __nv_bfloat16 g_intra_b[(size_t)BH_ * N_ * C_ * C_];
__device__ __nv_bfloat16 g_wkgT  [(size_t)BH_ * N_ * HD_ * C_];

__global__ __launch_bounds__(256) void conv_bf16(const float* __restrict__ in,
                                                 __nv_bfloat16* __restrict__ out) {
    size_t i = ((size_t)blockIdx.x * 256 + threadIdx.x) * 8;
    float4 a = *(const float4*)(in + i);
    float4 b = *(const float4*)(in + i + 4);
    __nv_bfloat162 r0 = __floats2bfloat162_rn(a.x, a.y);
    __nv_bfloat162 r1 = __floats2bfloat162_rn(a.z, a.w);
    __nv_bfloat162 r2 = __floats2bfloat162_rn(b.x, b.y);
    __nv_bfloat162 r3 = __floats2bfloat162_rn(b.z, b.w);
    uint4 pk;
    pk.x = *(unsigned*)&r0; pk.y = *(unsigned*)&r1;
    pk.z = *(unsigned*)&r2; pk.w = *(unsigned*)&r3;
    *(uint4*)(out + i) = pk;
}

// rk normalize + x->bf16, FUSED with Ww->bf16 conversion and setup.
__global__ __launch_bounds__(256) void rk_fused_kernel(const float* __restrict__ x,
                                                       const float* __restrict__ Ww,
                                                       const float* __restrict__ decay,
                                                       const float* __restrict__ log_alpha) {
    if (blockIdx.x >= 8192) {
        int cb = blockIdx.x - 8192;
        if (cb == 0 && threadIdx.x < H_) {
            int h = threadIdx.x;
            float g = 1.f / (1.f + expf(-decay[h]));
            g_alpha[h] = expf(log_alpha[h]);
            float p = 1.f;
            for (int i = 0; i <= C_; i++) { g_gpow[h][i] = p; p *= g; }
        }
        size_t i = ((size_t)cb * 256 + threadIdx.x) * 8;
        float4 a = *(const float4*)(Ww + i);
        float4 b = *(const float4*)(Ww + i + 4);
        __nv_bfloat162 r0 = __floats2bfloat162_rn(a.x, a.y);
        __nv_bfloat162 r1 = __floats2bfloat162_rn(a.z, a.w);
        __nv_bfloat162 r2 = __floats2bfloat162_rn(b.x, b.y);
        __nv_bfloat162 r3 = __floats2bfloat162_rn(b.z, b.w);
        uint4 pk;
        pk.x = *(unsigned*)&r0; pk.y = *(unsigned*)&r1;
        pk.z = *(unsigned*)&r2; pk.w = *(unsigned*)&r3;
        *(uint4*)(g_Wwb + i) = pk;
        return;
    }
    int warp = threadIdx.x >> 5, lane = threadIdx.x & 31;
    int row = blockIdx.x * 8 + warp;
    int h  = row & (H_ - 1);
    int bt = row >> 2;
    const float* xp = x + (size_t)bt * D_ + h * HD_ + lane * 8;
    float4 v0 = *(const float4*)(xp);
    float4 v1 = *(const float4*)(xp + 4);
    {
        __nv_bfloat162 q0 = __floats2bfloat162_rn(v0.x, v0.y);
        __nv_bfloat162 q1 = __floats2bfloat162_rn(v0.z, v0.w);
        __nv_bfloat162 q2 = __floats2bfloat162_rn(v1.x, v1.y);
        __nv_bfloat162 q3 = __floats2bfloat162_rn(v1.z, v1.w);
        uint4 pk;
        pk.x = *(unsigned*)&q0; pk.y = *(unsigned*)&q1;
        pk.z = *(unsigned*)&q2; pk.w = *(unsigned*)&q3;
        *(uint4*)(g_xb + (size_t)bt * D_ + h * HD_ + lane * 8) = pk;
    }
    float ss = v0.x*v0.x + v0.y*v0.y + v0.z*v0.z + v0.w*v0.w
             + v1.x*v1.x + v1.y*v1.y + v1.z*v1.z + v1.w*v1.w;
    #pragma unroll
    for (int o = 16; o; o >>= 1) ss += __shfl_xor_sync(0xffffffffu, ss, o);
    float inv = 1.f / fmaxf(sqrtf(ss), 1e-12f);
    int b = bt >> 13, t = bt & (T_ - 1);
    size_t base = ((size_t)(b * H_ + h) * T_ + t) * HD_ + lane * 8;
    float4 o0 = make_float4(v0.x*inv, v0.y*inv, v0.z*inv, v0.w*inv);
    float4 o1 = make_float4(v1.x*inv, v1.y*inv, v1.z*inv, v1.w*inv);
    *(float4*)(g_rk + base)     = o0;
    *(float4*)(g_rk + base + 4) = o1;
    __nv_bfloat162 q0 = __floats2bfloat162_rn(o0.x, o0.y);
    __nv_bfloat162 q1 = __floats2bfloat162_rn(o0.z, o0.w);
    __nv_bfloat162 q2 = __floats2bfloat162_rn(o1.x, o1.y);
    __nv_bfloat162 q3 = __floats2bfloat162_rn(o1.z, o1.w);
    uint4 pk;
    pk.x = *(unsigned*)&q0; pk.y = *(unsigned*)&q1;
    pk.z = *(unsigned*)&q2; pk.w = *(unsigned*)&q3;
    *(uint4*)(g_rkb + base) = pk;
}

// ---------------- bf16 GEMM (TN), cp.async 2-stage (proven R9) -------------
#define RSE 40
#define STG_B (128 * RSE * 2)
__global__ __launch_bounds__(256, 2) void gemm_bf16_tn(const __nv_bfloat16* __restrict__ A,
                                                       const __nv_bfloat16* __restrict__ W,
                                                       const float* __restrict__ Cin,
                                                       float* __restrict__ Cout) {
    __shared__ __nv_bfloat16 As[2][128 * RSE];
    __shared__ __nv_bfloat16 Bs[2][128 * RSE];
    const int tid = threadIdx.x;
    const int bm = blockIdx.y * 128, bn = blockIdx.x * 128;
    const int wid = tid >> 5, lane = tid & 31;
    const int wm = (wid & 3) * 32, wn = (wid >> 2) * 64;
    const int lr = tid >> 2, lk = (tid & 3) * 8;
    const __nv_bfloat16* Ap0 = A + (size_t)(bm + lr) * D_ + lk;
    const __nv_bfloat16* Ap1 = A + (size_t)(bm + lr + 64) * D_ + lk;
    const __nv_bfloat16* Wp0 = W + (size_t)(bn + lr) * D_ + lk;
    const __nv_bfloat16* Wp1 = W + (size_t)(bn + lr + 64) * D_ + lk;
    const unsigned dA = smem_u32(&As[0][lr * RSE + lk]);
    const unsigned dB = smem_u32(&Bs[0][lr * RSE + lk]);
    const unsigned a_base = smem_u32(As) +
        (unsigned)((wm + (lane & 7) + ((lane >> 3) & 1) * 8) * (RSE * 2) + (lane >> 4) * 16);
    const unsigned b_base = smem_u32(Bs) +
        (unsigned)((wn + (lane & 7) + ((lane >> 4) & 1) * 8) * (RSE * 2) + ((lane >> 3) & 1) * 16);

    float acc[2][8][4];
    #pragma unroll
    for (int mt = 0; mt < 2; mt++)
        #pragma unroll
        for (int nt = 0; nt < 8; nt++)
            #pragma unroll
            for (int q = 0; q < 4; q++) acc[mt][nt][q] = 0.f;

    auto loadStage = [&](int s, int k0) {
        CPA16(dA + s * STG_B, Ap0 + k0);
        CPA16(dA + s * STG_B + 64 * RSE * 2, Ap1 + k0);
        CPA16(dB + s * STG_B, Wp0 + k0);
        CPA16(dB + s * STG_B + 64 * RSE * 2, Wp1 + k0);
    };

    loadStage(0, 0);  CPCOMMIT();
    loadStage(1, 32); CPCOMMIT();

    for (int i = 0; i < 32; i++) {
        if (i < 31) { CPWAIT1(); } else { CPWAIT0(); }
        __syncthreads();
        const unsigned sa = a_base + (i & 1) * STG_B;
        const unsigned sbb = b_base + (i & 1) * STG_B;
        #pragma unroll
        for (int kk = 0; kk < 2; kk++) {
            unsigned ka = sa + kk * 32, kb = sbb + kk * 32;
            unsigned af[2][4], bf[4][4];
            #pragma unroll
            for (int mt = 0; mt < 2; mt++) LDSM4(af[mt], ka + mt * 16 * (RSE * 2));
            #pragma unroll
            for (int j = 0; j < 4; j++) LDSM4(bf[j], kb + j * 16 * (RSE * 2));
            #pragma unroll
            for (int mt = 0; mt < 2; mt++)
                #pragma unroll
                for (int nt = 0; nt < 8; nt++)
                    MMA16816(acc[mt][nt], af[mt],
                             bf[nt >> 1][(nt & 1) * 2 + 0], bf[nt >> 1][(nt & 1) * 2 + 1]);
        }
        __syncthreads();
        if (i + 2 < 32) { loadStage(i & 1, (i + 2) * 32); CPCOMMIT(); }
    }

    const int rr = lane >> 2, cc = (lane & 3) * 2;
    #pragma unroll
    for (int mt = 0; mt < 2; mt++) {
        int row = bm + wm + mt * 16 + rr;
        #pragma unroll
        for (int nt = 0; nt < 8; nt++) {
            int col = bn + wn + nt * 8 + cc;
            float2 lo = make_float2(acc[mt][nt][0], acc[mt][nt][1]);
            float2 hi = make_float2(acc[mt][nt][2], acc[mt][nt][3]);
            if (Cin) {
                float2 c0 = *(const float2*)(Cin + (size_t)row * D_ + col);
                float2 c1 = *(const float2*)(Cin + (size_t)(row + 8) * D_ + col);
                lo.x += c0.x; lo.y += c0.y; hi.x += c1.x; hi.y += c1.y;
            }
            *(float2*)(Cout + (size_t)row * D_ + col)       = lo;
            *(float2*)(Cout + (size_t)(row + 8) * D_ + col) = hi;
        }
    }
}

// ---------------- chunk prep: MMA phase 1 + forward substitution ------------
#define PSTK 0
#define PWL  34320
#define PGP  51728
#define PREP_SMEM 52096
__global__ __launch_bounds__(256) void prep_kernel() {
    extern __shared__ char smc[];
    const unsigned sb = smem_u32(smc);
    float* Wl  = (float*)(smc + PWL);
    float* gps = (float*)(smc + PGP);
    const int tid = threadIdx.x, wid = tid >> 5, lane = tid & 31;
    const int n  = blockIdx.x & (N_ - 1);
    const int bh = blockIdx.x >> 7;
    const int b  = bh >> 2, h = bh & 3;
    if (tid <= C_) gps[tid] = g_gpow[h][tid];

    const __nv_bfloat16* gRkb = g_rkb + (size_t)bh * T_ * HD_;
    const int t0 = n * C_ - 1;
    {
        int r = tid >> 2, seg = (tid & 3) * 64;
        int grow = t0 + r; if (grow < 0) grow = 0;
        unsigned d = sb + PSTK + r * 528 + seg * 2;
        const __nv_bfloat16* s = gRkb + (size_t)grow * HD_ + seg;
        #pragma unroll
        for (int q = 0; q < 8; q++) CPA16(d + q * 16, s + q * 8);
        if (tid < 4) {
            unsigned d2 = sb + PSTK + 64 * 528 + tid * 128;
            const __nv_bfloat16* s2 = gRkb + (size_t)(t0 + 64) * HD_ + tid * 64;
            #pragma unroll
            for (int q = 0; q < 8; q++) CPA16(d2 + q * 16, s2 + q * 8);
        }
    }
    CPCOMMIT(); CPWAIT0();
    __syncthreads();
    if (t0 < 0 && tid < 32) *(uint4*)(smc + PSTK + tid * 16) = make_uint4(0,0,0,0);
    __syncthreads();

    float acc[8][4];
    #pragma unroll
    for (int nt = 0; nt < 8; nt++)
        #pragma unroll
        for (int q = 0; q < 4; q++) acc[nt][q] = 0.f;
    {
        const unsigned abase = sb + PSTK +
            ((wid & 3) * 16 + (lane & 15) + (wid >= 4 ? 1 : 0)) * 528 + (lane >> 4) * 16;
        const unsigned bbase = sb + PSTK +
            ((lane & 7) + ((lane >> 4) & 1) * 8) * 528 + ((lane >> 3) & 1) * 16;
        #pragma unroll
        for (int k = 0; k < 16; k++) {
            unsigned af[4], bf4[4][4];
            LDSM4(af, abase + k * 32);
            #pragma unroll
            for (int j = 0; j < 4; j++) LDSM4(bf4[j], bbase + j * 16 * 528 + k * 32);
            #pragma unroll
            for (int nt = 0; nt < 8; nt++)
                MMA16816(acc[nt], af,
                         bf4[nt >> 1][(nt & 1) * 2 + 0], bf4[nt >> 1][(nt & 1) * 2 + 1]);
        }
    }
    size_t ib = ((size_t)(bh * N_ + n)) * C_;
    {
        const int rr = lane >> 2, cq = (lane & 3) * 2;
        const int i0 = (wid & 3) * 16 + rr;
        #pragma unroll
        for (int nt = 0; nt < 8; nt++) {
            int j = nt * 8 + cq;
            #pragma unroll
            for (int half = 0; half < 2; half++) {
                int i = i0 + half * 8;
                float v0 = acc[nt][half * 2 + 0], v1 = acc[nt][half * 2 + 1];
                float l0 = (j < i)     ? gps[i - j]     : 0.f;
                float l1 = (j + 1 < i) ? gps[i - j - 1] : 0.f;
                if (wid < 4) {
                    Wl[i * 68 + j]     = v0 * l0;
                    Wl[i * 68 + j + 1] = v1 * l1;
                } else {
                    *(__nv_bfloat162*)&g_intra_b[(ib + i) * C_ + j] =
                        __floats2bfloat162_rn(v0 * l0, v1 * l1);
                }
            }
        }
    }
    __syncthreads();

    const int c = tid;
    ull bvw[C_];
    const size_t wgbase = ((size_t)(bh * N_ + n) * HD_ + c) * C_;
    #pragma unroll
    for (int i2 = 0; i2 < C_ / 2; i2++) {
        int i = 2 * i2;
        float bv0 = g_v[((size_t)b * T_ + n * C_ + i) * D_ + h * HD_ + c];
        float bv1 = g_v[((size_t)b * T_ + n * C_ + i + 1) * D_ + h * HD_ + c];
        int tw0 = n * C_ + i - 1;
        float bw0 = (tw0 >= 0) ? g_rk[((size_t)bh * T_ + tw0) * HD_ + c] : 0.f;
        float bw1 = g_rk[((size_t)bh * T_ + tw0 + 1) * HD_ + c];
        bvw[i]     = pk2(bv0, bw0);
        bvw[i + 1] = pk2(bv1, bw1);
        __nv_bfloat162 wp;
        wp.x = __float2bfloat16(bw0 * gps[63 - i]);
        wp.y = __float2bfloat16(bw1 * gps[62 - i]);
        *(__nv_bfloat162*)&g_wkgT[wgbase + i] = wp;
    }
    #pragma unroll
    for (int i = 1; i < C_; i++) {
        ull a = 0ULL;
        #pragma unroll
        for (int j4 = 0; j4 < i; j4 += 4) {
            float4 w = *(const float4*)&Wl[i * 68 + j4];
            a = fma2(pk2(w.x, w.x), bvw[j4],     a);
            a = fma2(pk2(w.y, w.y), bvw[j4 + 1], a);
            a = fma2(pk2(w.z, w.z), bvw[j4 + 2], a);
            a = fma2(pk2(w.w, w.w), bvw[j4 + 3], a);
        }
        bvw[i] = add2(bvw[i], a ^ SGN2);
    }
    #pragma unroll
    for (int i = 0; i < C_; i++) {
        float2 f = upk2(bvw[i]);
        g_vcorr [(ib + i) * HD_ + c] = f.x;
        g_wkcA_b[(ib + i) * HD_ + c] = __float2bfloat16(f.y);
    }
}

// ---------------- MMA chunk scan: 128 CTAs x 512 thr, TMA-bulk copies ------
#define AST_OFF  0
#define AST_BUF  67584
#define WGT_OFF  135168
#define SB_OFF   172032
#define VNT_OFF  180480
#define INT_OFF  182784
#define VCO_OFF  192000
#define PART_OFF 201216
#define GP_OFF   209408
#define MBAR_OFF 209920
#define SCAN_SMEM 209984

__global__ void __launch_bounds__(512, 1) scan_mma_kernel() {
    extern __shared__ char smc[];
    const unsigned sb = smem_u32(smc);
    const int tid = threadIdx.x, wid = tid >> 5, lane = tid & 31;
    const int bh = blockIdx.y, c0 = blockIdx.x * 16;
    const int b = bh >> 2, h = bh & 3;
    float* gps = (float*)(smc + GP_OFF);
    if (tid <= C_) gps[tid] = g_gpow[h][tid];
    if (tid == C_ + 1) gps[C_ + 1] = g_alpha[h];

    const __nv_bfloat16* gWkc = g_wkcA_b + (size_t)bh * N_ * C_ * HD_;
    const __nv_bfloat16* gRk  = g_rkb    + (size_t)bh * T_ * HD_;
    const __nv_bfloat16* gWg  = g_wkgT   + (size_t)bh * N_ * HD_ * C_;
    const __nv_bfloat16* gIn  = g_intra_b+ (size_t)bh * N_ * C_ * C_;
    const float*         gVc  = g_vcorr  + (size_t)bh * N_ * C_ * HD_;

    const unsigned mbG1a = sb + MBAR_OFF;
    const unsigned mbG1b = sb + MBAR_OFF + 8;
    const unsigned mbG2  = sb + MBAR_OFF + 16;
    if (tid == 0) { MBAR_INIT(mbG1a, 1); MBAR_INIT(mbG1b, 1); MBAR_INIT(mbG2, 1); }
    asm volatile("fence.proxy.async;" ::: "memory");
    __syncthreads();

    // G1: A-stack, 128 rows x 512B bulk copies
    auto copyG1 = [&](int n) {
        unsigned mb = (n & 1) ? mbG1b : mbG1a;
        if (tid == 0) MBAR_EXPECT(mb, 65536);
        if (tid < 128) {
            unsigned d = sb + AST_OFF + (n & 1) * AST_BUF + tid * 528;
            const __nv_bfloat16* s = (tid < 64)
                ? gWkc + ((size_t)n * C_ + tid) * HD_
                : gRk  + ((size_t)n * C_ + (tid - 64)) * HD_;
            CPBULK(d, s, 512, mb);
        }
    };
    // G2: wkgT(256x128B) + intra(64x128B) + vco(64x64B) bulk copies
    auto copyG2 = [&](int n) {
        if (tid == 0) MBAR_EXPECT(mbG2, 45056);
        if (tid < 256) {
            CPBULK(sb + WGT_OFF + tid * 144, gWg + ((size_t)n * HD_ + tid) * C_, 128, mbG2);
        } else if (tid < 320) {
            int r = tid - 256;
            CPBULK(sb + INT_OFF + r * 144, gIn + ((size_t)n * C_ + r) * C_, 128, mbG2);
        } else if (tid < 384) {
            int r = tid - 320;
            CPBULK(sb + VCO_OFF + r * 144, gVc + ((size_t)n * C_ + r) * HD_ + c0, 64, mbG2);
        }
    };

    const int rt = wid & 7, kh = wid >> 3;
    const unsigned aA = sb + AST_OFF + (rt * 16 + (lane & 15)) * 528 + (lane >> 4) * 16 + kh * 256;
    const unsigned bS = sb + SB_OFF + ((lane & 7) + ((lane >> 4) & 1) * 8) * 528 + ((lane >> 3) & 1) * 16 + kh * 256;
    const unsigned aV = sb + VNT_OFF + (lane & 15) * 144 + (lane >> 4) * 16;
    const unsigned bW = sb + WGT_OFF + (wid * 16 + (lane & 7) + ((lane >> 4) & 1) * 8) * 144 + ((lane >> 3) & 1) * 16;
    const unsigned aI = sb + INT_OFF + ((wid & 3) * 16 + (lane & 15)) * 144 + (lane >> 4) * 16;
    const unsigned bV = sb + VNT_OFF + ((lane & 7) + ((lane >> 4) & 1) * 8) * 144 + ((lane >> 3) & 1) * 16;
    float* part = (float*)(smc + PART_OFF);

    float Sacc[2][4] = {};
    copyG1(0);
    copyG2(0);

    for (int n = 0; n < N_; n++) {
        #pragma unroll
        for (int nt = 0; nt < 2; nt++) {
            int c = lane >> 2;
            int ks = wid * 16 + nt * 8 + (lane & 3) * 2;
            *(__nv_bfloat162*)(smc + SB_OFF + c * 528 + ks * 2) =
                __floats2bfloat162_rn(Sacc[nt][0], Sacc[nt][1]);
            *(__nv_bfloat162*)(smc + SB_OFF + (c + 8) * 528 + ks * 2) =
                __floats2bfloat162_rn(Sacc[nt][2], Sacc[nt][3]);
        }
        if (n + 1 < N_) copyG1(n + 1);
        MBAR_WAIT((n & 1) ? mbG1b : mbG1a, (n >> 1) & 1);   // A-stack(n) resident
        __syncthreads();

        float accA[2][4] = {};
        {
            unsigned ab = aA + (n & 1) * AST_BUF;
            #pragma unroll
            for (int k = 0; k < 8; k++) {
                unsigned af[4], b0[4];
                LDSM4(af, ab + k * 32);
                LDSM4(b0, bS + k * 32);
                MMA16816(accA[0], af, b0[0], b0[1]);
                MMA16816(accA[1], af, b0[2], b0[3]);
            }
        }
        if (wid >= 8) {
            float* pp = part + (wid - 8) * 256 + lane * 8;
            *(float4*)pp       = make_float4(accA[0][0], accA[0][1], accA[0][2], accA[0][3]);
            *(float4*)(pp + 4) = make_float4(accA[1][0], accA[1][1], accA[1][2], accA[1][3]);
        }
        MBAR_WAIT(mbG2, n & 1);                             // G2(n) resident
        __syncthreads();

        int r0 = (wid & 3) * 16 + (lane >> 2);
        if (wid < 8) {
            float* pp = part + wid * 256 + lane * 8;
            float4 p0 = *(float4*)pp, p1 = *(float4*)(pp + 4);
            accA[0][0] += p0.x; accA[0][1] += p0.y; accA[0][2] += p0.z; accA[0][3] += p0.w;
            accA[1][0] += p1.x; accA[1][1] += p1.y; accA[1][2] += p1.z; accA[1][3] += p1.w;
        }
        if (wid < 4) {
            #pragma unroll
            for (int nt = 0; nt < 2; nt++) {
                int cc = nt * 8 + (lane & 3) * 2;
                float2 v0 = *(float2*)(smc + VCO_OFF + r0 * 144 + cc * 4);
                float2 v1 = *(float2*)(smc + VCO_OFF + (r0 + 8) * 144 + cc * 4);
                *(__nv_bfloat16*)(smc + VNT_OFF + cc * 144 + r0 * 2)       = __float2bfloat16(v0.x - accA[nt][0]);
                *(__nv_bfloat16*)(smc + VNT_OFF + (cc + 1) * 144 + r0 * 2) = __float2bfloat16(v0.y - accA[nt][1]);
                *(__nv_bfloat16*)(smc + VNT_OFF + cc * 144 + (r0 + 8) * 2)       = __float2bfloat16(v1.x - accA[nt][2]);
                *(__nv_bfloat16*)(smc + VNT_OFF + (cc + 1) * 144 + (r0 + 8) * 2) = __float2bfloat16(v1.y - accA[nt][3]);
            }
        } else if (wid < 8) {
            float g0 = gps[r0], g1 = gps[r0 + 8];
            #pragma unroll
            for (int nt = 0; nt < 2; nt++) {
                accA[nt][0] *= g0; accA[nt][1] *= g0;
                accA[nt][2] *= g1; accA[nt][3] *= g1;
            }
        }
        __syncthreads();

        if (wid >= 4 && wid < 8) {
            #pragma unroll
            for (int k = 0; k < 4; k++) {
                unsigned ai[4], v0[4];
                LDSM4(ai, aI + k * 32);
                LDSM4(v0, bV + k * 32);
                MMA16816(accA[0], ai, v0[0], v0[1]);
                MMA16816(accA[1], ai, v0[2], v0[3]);
            }
            float al = gps[C_ + 1];
            size_t ob = ((size_t)b * T_ + n * C_) * D_ + h * HD_ + c0;
            #pragma unroll
            for (int nt = 0; nt < 2; nt++) {
                int cc = nt * 8 + (lane & 3) * 2;
                *(__nv_bfloat162*)(g_ob + ob + (size_t)r0 * D_ + cc) =
                    __floats2bfloat162_rn(accA[nt][0] * al, accA[nt][1] * al);
                *(__nv_bfloat162*)(g_ob + ob + (size_t)(r0 + 8) * D_ + cc) =
                    __floats2bfloat162_rn(accA[nt][2] * al, accA[nt][3] * al);
            }
        }

        {
            float gC = gps[C_];
            #pragma unroll
            for (int nt = 0; nt < 2; nt++)
                #pragma unroll
                for (int q = 0; q < 4; q++) Sacc[nt][q] *= gC;
            #pragma unroll
            for (int k = 0; k < 4; k++) {
                unsigned a0[4], w0[4];
                LDSM4(a0, aV + k * 32);
                LDSM4(w0, bW + k * 32);
                MMA16816(Sacc[0], a0, w0[0], w0[1]);
                MMA16816(Sacc[1], a0, w0[2], w0[3]);
            }
        }
        __syncthreads();
        if (n + 1 < N_) copyG2(n + 1);
    }
}

// ---------------- launch ----------------
extern "C" void kernel_launch(void* const* d_in, const int* in_sizes, int n_in,
                              void* d_out, int out_size) {
    const float* x     = (const float*)d_in[0];
    const float* Ww    = (const float*)d_in[1];
    const float* Wr    = (const float*)d_in[2];
    const float* decay = (const float*)d_in[3];
    const float* lalp  = (const float*)d_in[4];
    float* out = (float*)d_out;

    cudaFuncSetAttribute(scan_mma_kernel, cudaFuncAttributeMaxDynamicSharedMemorySize,
                         SCAN_SMEM);
    cudaFuncSetAttribute(prep_kernel, cudaFuncAttributeMaxDynamicSharedMemorySize,
                         PREP_SMEM);

    void *pv = nullptr, *pxb = nullptr, *pob = nullptr, *pwwb = nullptr, *pwrb = nullptr;
    cudaGetSymbolAddress(&pv, g_v);
    cudaGetSymbolAddress(&pxb, g_xb);
    cudaGetSymbolAddress(&pob, g_ob);
    cudaGetSymbolAddress(&pwwb, g_Wwb);
    cudaGetSymbolAddress(&pwrb, g_Wrb);

    const size_t NW = (size_t)D_ * D_;

    // launch order keeps scan at profiled index 3
    rk_fused_kernel<<<8192 + 512, 256>>>(x, Ww, decay, lalp);
    gemm_bf16_tn<<<dim3(D_ / 128, (B_ * T_) / 128), 256>>>(
        (const __nv_bfloat16*)pxb, (const __nv_bfloat16*)pwwb, nullptr, (float*)pv);
    prep_kernel<<<BH_ * N_, 256, PREP_SMEM>>>();
    scan_mma_kernel<<<dim3(16, BH_), 512, SCAN_SMEM>>>();
    conv_bf16<<<(int)(NW / 2048), 256>>>(Wr, (__nv_bfloat16*)pwrb);
    gemm_bf16_tn<<<dim3(D_ / 128, (B_ * T_) / 128), 256>>>(
        (const __nv_bfloat16*)pob, (const __nv_bfloat16*)pwrb, x, out);
}